// round 5
// baseline (speedup 1.0000x reference)
#include <cuda_runtime.h>
#include <cuda_bf16.h>
#include <cstdint>

// ---------------------------------------------------------------------------
// CrossAttention: B=1, I=J=1024, C_S=1024, H=16, D=64, C_Z=128
// Round 5: no tcgen05 on this toolchain target (compute_103). All heavy GEMMs
// on mma.sync HMMA with cp.async double-buffered pipeline, 2 CTAs/SM,
// q/k/v/g fused into one jobs launch. hi/lo bf16 3-term split for fp32 acc.
// ---------------------------------------------------------------------------

#define NN 1024
#define HEADS 16
#define HD 64
#define CZ 128

typedef __nv_bfloat16 bf16;
typedef __nv_bfloat162 bf162;

// ---------------- scratch (device globals; allocation forbidden) -----------
__device__ bf16 g_sh [NN * NN], g_sl [NN * NN];
__device__ bf16 g_kih[NN * NN], g_kil[NN * NN];
__device__ bf16 g_Wqh[NN * NN], g_Wql[NN * NN];
__device__ bf16 g_Wkh[NN * NN], g_Wkl[NN * NN];
__device__ bf16 g_Wvh[NN * NN], g_Wvl[NN * NN];
__device__ bf16 g_Wgh[NN * NN], g_Wgl[NN * NN];
__device__ bf16 g_Woh[NN * NN], g_Wol[NN * NN];
__device__ bf16 g_qh [NN * NN], g_ql [NN * NN];
__device__ bf16 g_kh [NN * NN], g_kl [NN * NN];
__device__ bf16 g_vth[NN * NN], g_vtl[NN * NN];   // transposed V: [c_s][j]
__device__ float g_g [NN * NN];
__device__ float g_z [HEADS * NN * NN];           // logits, 64 MB
__device__ bf16 g_ph [HEADS * NN * NN], g_pl[HEADS * NN * NN];
__device__ float g_o [NN * NN];
__device__ bf16 g_goh[NN * NN], g_gol[NN * NN];

// ---------------------------------------------------------------------------
// helpers
// ---------------------------------------------------------------------------
__device__ __forceinline__ void bsplit(float v, bf16& h, bf16& l) {
    h = __float2bfloat16(v);
    l = __float2bfloat16(v - __bfloat162float(h));
}

__device__ __forceinline__ uint32_t smem_u32(const void* p) {
    return (uint32_t)__cvta_generic_to_shared(p);
}

__device__ __forceinline__ void cpasync16(uint32_t dst, const void* src) {
    asm volatile("cp.async.cg.shared.global [%0], [%1], 16;\n"
                 :: "r"(dst), "l"(src));
}
__device__ __forceinline__ void cp_commit() {
    asm volatile("cp.async.commit_group;\n" ::: "memory");
}
template <int N> __device__ __forceinline__ void cp_wait() {
    asm volatile("cp.async.wait_group %0;\n" :: "n"(N) : "memory");
}

__device__ __forceinline__ void mma16816(float* d, const uint32_t* a,
                                         uint32_t b0, uint32_t b1) {
    asm volatile(
        "mma.sync.aligned.m16n8k16.row.col.f32.bf16.bf16.f32 "
        "{%0,%1,%2,%3}, {%4,%5,%6,%7}, {%8,%9}, {%0,%1,%2,%3};\n"
        : "+f"(d[0]), "+f"(d[1]), "+f"(d[2]), "+f"(d[3])
        : "r"(a[0]), "r"(a[1]), "r"(a[2]), "r"(a[3]), "r"(b0), "r"(b1));
}

__device__ __forceinline__ void ldsm4(uint32_t* r, const void* p) {
    uint32_t a = (uint32_t)__cvta_generic_to_shared(p);
    asm volatile("ldmatrix.sync.aligned.m8n8.x4.shared.b16 {%0,%1,%2,%3}, [%4];\n"
                 : "=r"(r[0]), "=r"(r[1]), "=r"(r[2]), "=r"(r[3]) : "r"(a));
}

// ---------------------------------------------------------------------------
// Pipelined split-bf16 NT GEMM body. BM=128, BN=64, BK=32, 256 threads,
// double-buffered cp.async. Dynamic smem layout (bf16 elems):
//   As[2buf][2kh][2hl][128][24]  = 24576 elems (49152 B)
//   Bs[2buf][2kh][2hl][ 64][24]  = 12288 elems (24576 B)   total 73728 B
// ---------------------------------------------------------------------------
#define ASZ_ELEMS (2 * 2 * 2 * 128 * 24)
#define PIPE_SMEM 73728

__device__ __forceinline__ void gemm_body(
    bf16* sm,
    const bf16* __restrict__ Abh, const bf16* __restrict__ Abl,
    const bf16* __restrict__ Bbh, const bf16* __restrict__ Bbl,
    int lda, int ldb,
    const float* __restrict__ bias, const float* __restrict__ CinB,
    float* __restrict__ Cf, bf16* __restrict__ Oh, bf16* __restrict__ Ol,
    int ldc, long long obase,
    int K, float alpha, int mode, int act,
    int bx, int by)
{
    const int tid = threadIdx.x, lane = tid & 31, warp = tid >> 5;
    const int wm = warp & 3, wn = warp >> 2;
    const int arow0 = tid >> 2, akc = tid & 3, brow = tid >> 2;
    const int ldsr = lane & 15;
    const int ldsc = (lane & 16) ? 8 : 0;

    const uint32_t smb = smem_u32(sm);

    auto As_a = [&](int buf, int kh, int hl, int r, int c) -> uint32_t {
        return smb + ((((((buf * 2 + kh) * 2 + hl) * 128 + r) * 24) + c) << 1);
    };
    auto Bs_a = [&](int buf, int kh, int hl, int r, int c) -> uint32_t {
        return smb + ((ASZ_ELEMS + ((((buf * 2 + kh) * 2 + hl) * 64 + r) * 24) + c) << 1);
    };
    auto As_p = [&](int buf, int kh, int hl) -> bf16* {
        return sm + ((buf * 2 + kh) * 2 + hl) * 128 * 24;
    };
    auto Bs_p = [&](int buf, int kh, int hl) -> bf16* {
        return sm + ASZ_ELEMS + ((buf * 2 + kh) * 2 + hl) * 64 * 24;
    };

    auto load = [&](int buf, int k0) {
#pragma unroll
        for (int t = 0; t < 2; t++) {
            int r = arow0 + t * 64;
            cpasync16(As_a(buf, akc >> 1, 0, r, (akc & 1) * 8),
                      Abh + (long long)r * lda + k0 + akc * 8);
            cpasync16(As_a(buf, akc >> 1, 1, r, (akc & 1) * 8),
                      Abl + (long long)r * lda + k0 + akc * 8);
        }
        cpasync16(Bs_a(buf, akc >> 1, 0, brow, (akc & 1) * 8),
                  Bbh + (long long)brow * ldb + k0 + akc * 8);
        cpasync16(Bs_a(buf, akc >> 1, 1, brow, (akc & 1) * 8),
                  Bbl + (long long)brow * ldb + k0 + akc * 8);
    };

    float d[2][4][4];
#pragma unroll
    for (int mt = 0; mt < 2; mt++)
#pragma unroll
        for (int nt = 0; nt < 4; nt++)
#pragma unroll
            for (int e = 0; e < 4; e++) d[mt][nt][e] = 0.f;

    const int iters = K / 32;
    load(0, 0);
    cp_commit();
    if (iters > 1) load(1, 32);
    cp_commit();

    for (int s = 0; s < iters; s++) {
        const int b = s & 1;
        cp_wait<1>();
        __syncthreads();
#pragma unroll
        for (int kh = 0; kh < 2; kh++) {
            uint32_t ah[2][4], al[2][4], bh[2][4], bl[2][4];
            bf16* ApH = As_p(b, kh, 0);
            bf16* ApL = As_p(b, kh, 1);
            bf16* BpH = Bs_p(b, kh, 0);
            bf16* BpL = Bs_p(b, kh, 1);
#pragma unroll
            for (int mt = 0; mt < 2; mt++) {
                int r = wm * 32 + mt * 16 + ldsr;
                ldsm4(ah[mt], ApH + r * 24 + ldsc);
                ldsm4(al[mt], ApL + r * 24 + ldsc);
            }
#pragma unroll
            for (int np = 0; np < 2; np++) {
                int r = wn * 32 + np * 16 + ldsr;
                ldsm4(bh[np], BpH + r * 24 + ldsc);
                ldsm4(bl[np], BpL + r * 24 + ldsc);
            }
#pragma unroll
            for (int mt = 0; mt < 2; mt++)
#pragma unroll
                for (int nt = 0; nt < 4; nt++) {
                    int np = nt >> 1, sel = nt & 1;
                    uint32_t bh0 = bh[np][sel], bh1 = bh[np][sel + 2];
                    uint32_t bl0 = bl[np][sel], bl1 = bl[np][sel + 2];
                    mma16816(d[mt][nt], ah[mt], bh0, bh1);   // hi*hi
                    mma16816(d[mt][nt], ah[mt], bl0, bl1);   // hi*lo
                    mma16816(d[mt][nt], al[mt], bh0, bh1);   // lo*hi
                }
        }
        __syncthreads();
        if (s + 2 < iters) load(b, (s + 2) * 32);
        cp_commit();
    }

    // ---- epilogue ----
    const int g = lane >> 2, tig = lane & 3;

#pragma unroll
    for (int mt = 0; mt < 2; mt++) {
#pragma unroll
        for (int nt = 0; nt < 4; nt++) {
            int c = bx * 64 + wn * 32 + nt * 8 + tig * 2;
#pragma unroll
            for (int half = 0; half < 2; half++) {
                int r = by * 128 + wm * 32 + mt * 16 + g + half * 8;
                float v0 = alpha * d[mt][nt][half * 2 + 0];
                float v1 = alpha * d[mt][nt][half * 2 + 1];
                if (CinB) {
                    float2 ci = *(const float2*)(CinB + (long long)r * ldc + c);
                    v0 += ci.x; v1 += ci.y;
                }
                if (bias) { v0 += bias[c]; v1 += bias[c + 1]; }
                if (act == 1) {
                    v0 = 1.f / (1.f + __expf(-v0));
                    v1 = 1.f / (1.f + __expf(-v1));
                }
                if (mode == 0) {
                    float2 ov = {v0, v1};
                    *(float2*)(Cf + obase + (long long)r * ldc + c) = ov;
                } else if (mode == 1) {
                    bf16 h0, h1, l0, l1;
                    bsplit(v0, h0, l0); bsplit(v1, h1, l1);
                    *(bf162*)(Oh + obase + (long long)r * ldc + c) = bf162{h0, h1};
                    *(bf162*)(Ol + obase + (long long)r * ldc + c) = bf162{l0, l1};
                } else {  // transposed [n][m]
                    bf16 h0, h1, l0, l1;
                    bsplit(v0, h0, l0); bsplit(v1, h1, l1);
                    Oh[obase + (long long)c * ldc + r]       = h0;
                    Oh[obase + (long long)(c + 1) * ldc + r] = h1;
                    Ol[obase + (long long)c * ldc + r]       = l0;
                    Ol[obase + (long long)(c + 1) * ldc + r] = l1;
                }
            }
        }
    }
}

// ---------------------------------------------------------------------------
// parameterized wrapper (heads batching via blockIdx.z)
// ---------------------------------------------------------------------------
__global__ void __launch_bounds__(256, 2)
bsgemm_pipe(const bf16* __restrict__ Ah, const bf16* __restrict__ Al,
            int lda, long long bsA,
            const bf16* __restrict__ Bh, const bf16* __restrict__ Bl,
            int ldb, long long bsB,
            const float* __restrict__ bias,
            const float* __restrict__ Cin, long long bsCin,
            float* __restrict__ Cf, bf16* __restrict__ Oh, bf16* __restrict__ Ol,
            int ldc, long long bsC,
            int K, float alpha, int mode, int act)
{
    extern __shared__ __align__(16) char smraw[];
    bf16* sm = (bf16*)smraw;
    const int bx = blockIdx.x, by = blockIdx.y, bz = blockIdx.z;
    gemm_body(sm,
              Ah + bz * bsA + (long long)by * 128 * lda,
              Al + bz * bsA + (long long)by * 128 * lda,
              Bh + bz * bsB + (long long)bx * 64 * ldb,
              Bl + bz * bsB + (long long)bx * 64 * ldb,
              lda, ldb, bias,
              Cin ? (Cin + bz * bsCin) : nullptr,
              Cf, Oh, Ol, ldc, bz * bsC,
              K, alpha, mode, act, bx, by);
}

// ---------------------------------------------------------------------------
// fused jobs wrapper (blockIdx.z selects job) for the square GEMMs
// ---------------------------------------------------------------------------
struct Job {
    const bf16 *Ah, *Al, *Bh, *Bl;
    const float* bias;
    float* Cf; bf16* Oh; bf16* Ol;
    int mode; int act;
};
struct Jobs4 { Job j[4]; };

__global__ void __launch_bounds__(256, 2)
bsgemm_jobs(Jobs4 jobs)
{
    extern __shared__ __align__(16) char smraw[];
    bf16* sm = (bf16*)smraw;
    const Job jb = jobs.j[blockIdx.z];
    const int bx = blockIdx.x, by = blockIdx.y;
    gemm_body(sm,
              jb.Ah + (long long)by * 128 * NN,
              jb.Al + (long long)by * 128 * NN,
              jb.Bh + (long long)bx * 64 * NN,
              jb.Bl + (long long)bx * 64 * NN,
              NN, NN, jb.bias, nullptr,
              jb.Cf, jb.Oh, jb.Ol, NN, 0,
              NN, 1.f, jb.mode, jb.act, bx, by);
}

// ---------------------------------------------------------------------------
// fused fp32 -> bf16 hi/lo split for 7 tensors (grid.y = tensor)
// ---------------------------------------------------------------------------
struct SplitJobs {
    const float* src[7];
    bf16* dh[7];
    bf16* dl[7];
};

__global__ void __launch_bounds__(256)
conv_split7(SplitJobs js)
{
    const float* x = js.src[blockIdx.y];
    bf16* xh = js.dh[blockIdx.y];
    bf16* xl = js.dl[blockIdx.y];
    int idx = blockIdx.x * 256 + threadIdx.x;
    float4 v = ((const float4*)x)[idx];
    bf16 h0, h1, h2, h3, l0, l1, l2, l3;
    bsplit(v.x, h0, l0); bsplit(v.y, h1, l1);
    bsplit(v.z, h2, l2); bsplit(v.w, h3, l3);
    bf162* H = (bf162*)(xh + idx * 4);
    bf162* L = (bf162*)(xl + idx * 4);
    H[0] = bf162{h0, h1}; H[1] = bf162{h2, h3};
    L[0] = bf162{l0, l1}; L[1] = bf162{l2, l3};
}

// ---------------------------------------------------------------------------
// z projection: z[h, p] = sum_c bias[p, c] * Wz[c, h] + (1-mask[j])*(-1e6)
// ---------------------------------------------------------------------------
__global__ void __launch_bounds__(128)
zproj_kernel(const float* __restrict__ bias, const float* __restrict__ Wz,
             const float* __restrict__ mask, float* __restrict__ z)
{
    __shared__ float bs[64][129];
    __shared__ float wzs[128][16];

    const int tid = threadIdx.x;
    const long long p0 = (long long)blockIdx.x * 64;

    for (int e = tid; e < CZ * HEADS; e += 128)
        wzs[e >> 4][e & 15] = Wz[e];

    const int c4 = tid & 31;
    const int r0 = tid >> 5;
#pragma unroll
    for (int r = r0; r < 64; r += 4) {
        float4 v = *(const float4*)(bias + (p0 + r) * CZ + c4 * 4);
        bs[r][c4 * 4 + 0] = v.x;
        bs[r][c4 * 4 + 1] = v.y;
        bs[r][c4 * 4 + 2] = v.z;
        bs[r][c4 * 4 + 3] = v.w;
    }
    __syncthreads();

    const int pair = tid & 63;
    const int hh = (tid >> 6) * 8;

    float acc[8];
#pragma unroll
    for (int h = 0; h < 8; h++) acc[h] = 0.f;

#pragma unroll 8
    for (int c = 0; c < CZ; c++) {
        float bv = bs[pair][c];
        float4 w0 = *(const float4*)&wzs[c][hh];
        float4 w1 = *(const float4*)&wzs[c][hh + 4];
        acc[0] += bv * w0.x; acc[1] += bv * w0.y;
        acc[2] += bv * w0.z; acc[3] += bv * w0.w;
        acc[4] += bv * w1.x; acc[5] += bv * w1.y;
        acc[6] += bv * w1.z; acc[7] += bv * w1.w;
    }

    const long long p = p0 + pair;
    const int j = (int)(p & (NN - 1));
    const float madd = (1.0f - mask[j]) * (-1000000.0f);
#pragma unroll
    for (int h = 0; h < 8; h++)
        z[(long long)(hh + h) * (NN * NN) + p] = acc[h] + madd;
}

// ---------------------------------------------------------------------------
// Row softmax -> probs bf16 hi/lo
// ---------------------------------------------------------------------------
__global__ void __launch_bounds__(256)
softmax_kernel(const float* __restrict__ z, bf16* __restrict__ ph,
               bf16* __restrict__ pl)
{
    const long long rb = (long long)blockIdx.x * NN;
    const float4* row = (const float4*)(z + rb);
    const int tid = threadIdx.x;
    float4 v = row[tid];

    __shared__ float red[8];

    float m = fmaxf(fmaxf(v.x, v.y), fmaxf(v.z, v.w));
#pragma unroll
    for (int o = 16; o; o >>= 1) m = fmaxf(m, __shfl_xor_sync(0xffffffffu, m, o));
    if ((tid & 31) == 0) red[tid >> 5] = m;
    __syncthreads();
    float bm = fmaxf(fmaxf(fmaxf(red[0], red[1]), fmaxf(red[2], red[3])),
                     fmaxf(fmaxf(red[4], red[5]), fmaxf(red[6], red[7])));
    __syncthreads();

    v.x = __expf(v.x - bm); v.y = __expf(v.y - bm);
    v.z = __expf(v.z - bm); v.w = __expf(v.w - bm);
    float s = v.x + v.y + v.z + v.w;
#pragma unroll
    for (int o = 16; o; o >>= 1) s += __shfl_xor_sync(0xffffffffu, s, o);
    if ((tid & 31) == 0) red[tid >> 5] = s;
    __syncthreads();
    float bsu = red[0] + red[1] + red[2] + red[3]
              + red[4] + red[5] + red[6] + red[7];
    float inv = 1.0f / bsu;
    v.x *= inv; v.y *= inv; v.z *= inv; v.w *= inv;

    bf16 h0, h1, h2, h3, l0, l1, l2, l3;
    bsplit(v.x, h0, l0); bsplit(v.y, h1, l1);
    bsplit(v.z, h2, l2); bsplit(v.w, h3, l3);
    bf162* H = (bf162*)(ph + rb + tid * 4);
    bf162* L = (bf162*)(pl + rb + tid * 4);
    H[0] = bf162{h0, h1}; H[1] = bf162{h2, h3};
    L[0] = bf162{l0, l1}; L[1] = bf162{l2, l3};
}

// ---------------------------------------------------------------------------
// go = g * o -> bf16 hi/lo
// ---------------------------------------------------------------------------
__global__ void __launch_bounds__(256)
mul_split_kernel(const float* __restrict__ a, const float* __restrict__ b,
                 bf16* __restrict__ ch, bf16* __restrict__ cl)
{
    int idx = blockIdx.x * 256 + threadIdx.x;
    float4 av = ((const float4*)a)[idx];
    float4 bv = ((const float4*)b)[idx];
    float4 cv;
    cv.x = av.x * bv.x; cv.y = av.y * bv.y;
    cv.z = av.z * bv.z; cv.w = av.w * bv.w;
    bf16 h0, h1, h2, h3, l0, l1, l2, l3;
    bsplit(cv.x, h0, l0); bsplit(cv.y, h1, l1);
    bsplit(cv.z, h2, l2); bsplit(cv.w, h3, l3);
    bf162* H = (bf162*)(ch + idx * 4);
    bf162* L = (bf162*)(cl + idx * 4);
    H[0] = bf162{h0, h1}; H[1] = bf162{h2, h3};
    L[0] = bf162{l0, l1}; L[1] = bf162{l2, l3};
}

// ---------------------------------------------------------------------------
extern "C" void kernel_launch(void* const* d_in, const int* in_sizes, int n_in,
                              void* d_out, int out_size)
{
    (void)in_sizes; (void)n_in; (void)out_size;

    const float* s    = (const float*)d_in[0];
    const float* kin  = (const float*)d_in[1];
    const float* mask = (const float*)d_in[2];
    const float* bias = (const float*)d_in[3];
    const float* Wq   = (const float*)d_in[4];
    const float* bq   = (const float*)d_in[5];
    const float* Wk   = (const float*)d_in[6];
    const float* Wv   = (const float*)d_in[7];
    const float* Wg   = (const float*)d_in[8];
    const float* Wo   = (const float*)d_in[9];
    const float* Wz   = (const float*)d_in[10];
    float* out = (float*)d_out;

    bf16 *sh, *sl, *kih, *kil, *Wqh, *Wql, *Wkh, *Wkl, *Wvh, *Wvl;
    bf16 *Wgh, *Wgl, *Woh, *Wol, *qh, *ql, *kh, *kl, *vth, *vtl;
    bf16 *ph, *pl, *goh, *gol;
    float *gg, *z, *o;
    cudaGetSymbolAddress((void**)&sh,  g_sh);  cudaGetSymbolAddress((void**)&sl,  g_sl);
    cudaGetSymbolAddress((void**)&kih, g_kih); cudaGetSymbolAddress((void**)&kil, g_kil);
    cudaGetSymbolAddress((void**)&Wqh, g_Wqh); cudaGetSymbolAddress((void**)&Wql, g_Wql);
    cudaGetSymbolAddress((void**)&Wkh, g_Wkh); cudaGetSymbolAddress((void**)&Wkl, g_Wkl);
    cudaGetSymbolAddress((void**)&Wvh, g_Wvh); cudaGetSymbolAddress((void**)&Wvl, g_Wvl);
    cudaGetSymbolAddress((void**)&Wgh, g_Wgh); cudaGetSymbolAddress((void**)&Wgl, g_Wgl);
    cudaGetSymbolAddress((void**)&Woh, g_Woh); cudaGetSymbolAddress((void**)&Wol, g_Wol);
    cudaGetSymbolAddress((void**)&qh,  g_qh);  cudaGetSymbolAddress((void**)&ql,  g_ql);
    cudaGetSymbolAddress((void**)&kh,  g_kh);  cudaGetSymbolAddress((void**)&kl,  g_kl);
    cudaGetSymbolAddress((void**)&vth, g_vth); cudaGetSymbolAddress((void**)&vtl, g_vtl);
    cudaGetSymbolAddress((void**)&ph,  g_ph);  cudaGetSymbolAddress((void**)&pl,  g_pl);
    cudaGetSymbolAddress((void**)&goh, g_goh); cudaGetSymbolAddress((void**)&gol, g_gol);
    cudaGetSymbolAddress((void**)&gg,  g_g);
    cudaGetSymbolAddress((void**)&z,   g_z);
    cudaGetSymbolAddress((void**)&o,   g_o);

    cudaFuncSetAttribute(bsgemm_pipe, cudaFuncAttributeMaxDynamicSharedMemorySize,
                         PIPE_SMEM);
    cudaFuncSetAttribute(bsgemm_jobs, cudaFuncAttributeMaxDynamicSharedMemorySize,
                         PIPE_SMEM);

    // split all fp32 operands to hi/lo (one launch)
    SplitJobs sj;
    sj.src[0] = s;   sj.dh[0] = sh;  sj.dl[0] = sl;
    sj.src[1] = kin; sj.dh[1] = kih; sj.dl[1] = kil;
    sj.src[2] = Wq;  sj.dh[2] = Wqh; sj.dl[2] = Wql;
    sj.src[3] = Wk;  sj.dh[3] = Wkh; sj.dl[3] = Wkl;
    sj.src[4] = Wv;  sj.dh[4] = Wvh; sj.dl[4] = Wvl;
    sj.src[5] = Wg;  sj.dh[5] = Wgh; sj.dl[5] = Wgl;
    sj.src[6] = Wo;  sj.dh[6] = Woh; sj.dl[6] = Wol;
    conv_split7<<<dim3((NN * NN) / (256 * 4), 7), 256>>>(sj);

    // fused q/k/v/g projections (jobs)
    Jobs4 j4;
    j4.j[0] = Job{sh,  sl,  Wqh, Wql, bq,      nullptr, qh,  ql,  1, 0};
    j4.j[1] = Job{kih, kil, Wkh, Wkl, nullptr, nullptr, kh,  kl,  1, 0};
    j4.j[2] = Job{kih, kil, Wvh, Wvl, nullptr, nullptr, vth, vtl, 2, 0};
    j4.j[3] = Job{sh,  sl,  Wgh, Wgl, nullptr, gg,      nullptr, nullptr, 0, 1};
    bsgemm_jobs<<<dim3(16, 8, 4), 256, PIPE_SMEM>>>(j4);

    // z = bias @ Wz + mask
    zproj_kernel<<<(NN * NN) / 64, 128>>>(bias, Wz, mask, z);

    const long long ZST = (long long)NN * NN;
    // logits = 0.125 * Qh @ Kh^T + z
    bsgemm_pipe<<<dim3(16, 8, HEADS), 256, PIPE_SMEM>>>(
        qh, ql, NN, HD, kh, kl, NN, HD,
        nullptr, z, ZST, z, nullptr, nullptr,
        NN, ZST, HD, 0.125f, 0, 0);
    // softmax -> probs hi/lo
    softmax_kernel<<<HEADS * NN, 256>>>(z, ph, pl);
    // O_h = P_h @ V_h (NT against transposed V)
    bsgemm_pipe<<<dim3(1, 8, HEADS), 256, PIPE_SMEM>>>(
        ph, pl, NN, ZST, vth, vtl, NN, (long long)HD * NN,
        nullptr, nullptr, 0, o, nullptr, nullptr,
        NN, HD, NN, 1.f, 0, 0);
    // go = g * o -> hi/lo
    mul_split_kernel<<<(NN * NN) / (256 * 4), 256>>>(gg, o, goh, gol);
    // out = go @ Wo^T
    Jobs4 jf;
    jf.j[0] = Job{goh, gol, Woh, Wol, nullptr, out, nullptr, nullptr, 0, 0};
    jf.j[1] = jf.j[0]; jf.j[2] = jf.j[0]; jf.j[3] = jf.j[0];
    bsgemm_jobs<<<dim3(16, 8, 1), 256, PIPE_SMEM>>>(jf);
}

// round 7
// speedup vs baseline: 1.5937x; 1.5937x over previous
#include <cuda_runtime.h>
#include <cuda_bf16.h>
#include <cstdint>

// ---------------------------------------------------------------------------
// CrossAttention: B=1, I=J=1024, C_S=1024, H=16, D=64, C_Z=128
// Round 6: revert GEMM core to round-3 (measured best). NEW: flash-fused
// logits+softmax+PV (z read once, no probs/logits round-trips to DRAM).
// ---------------------------------------------------------------------------

#define NN 1024
#define HEADS 16
#define HD 64
#define CZ 128

typedef __nv_bfloat16 bf16;
typedef __nv_bfloat162 bf162;

// ---------------- scratch (device globals; allocation forbidden) -----------
__device__ bf16 g_sh [NN * NN], g_sl [NN * NN];
__device__ bf16 g_kih[NN * NN], g_kil[NN * NN];
__device__ bf16 g_Wqh[NN * NN], g_Wql[NN * NN];
__device__ bf16 g_Wkh[NN * NN], g_Wkl[NN * NN];
__device__ bf16 g_Wvh[NN * NN], g_Wvl[NN * NN];
__device__ bf16 g_Wgh[NN * NN], g_Wgl[NN * NN];
__device__ bf16 g_Woh[NN * NN], g_Wol[NN * NN];
__device__ bf16 g_qh [NN * NN], g_ql [NN * NN];
__device__ bf16 g_kh [NN * NN], g_kl [NN * NN];
__device__ bf16 g_vth[NN * NN], g_vtl[NN * NN];   // transposed V: [c_s][j]
__device__ float g_g [NN * NN];
__device__ float g_z [HEADS * NN * NN];           // zproj output, 64 MB
__device__ float g_o [NN * NN];
__device__ bf16 g_goh[NN * NN], g_gol[NN * NN];

// ---------------------------------------------------------------------------
// helpers
// ---------------------------------------------------------------------------
__device__ __forceinline__ void bsplit(float v, bf16& h, bf16& l) {
    h = __float2bfloat16(v);
    l = __float2bfloat16(v - __bfloat162float(h));
}

__device__ __forceinline__ uint32_t smem_u32(const void* p) {
    return (uint32_t)__cvta_generic_to_shared(p);
}

__device__ __forceinline__ void cpasync16(uint32_t dst, const void* src) {
    asm volatile("cp.async.cg.shared.global [%0], [%1], 16;\n"
                 :: "r"(dst), "l"(src));
}
__device__ __forceinline__ void cp_commit() {
    asm volatile("cp.async.commit_group;\n" ::: "memory");
}
template <int N> __device__ __forceinline__ void cp_wait() {
    asm volatile("cp.async.wait_group %0;\n" :: "n"(N) : "memory");
}

__device__ __forceinline__ void mma16816(float* d, const uint32_t* a,
                                         uint32_t b0, uint32_t b1) {
    asm volatile(
        "mma.sync.aligned.m16n8k16.row.col.f32.bf16.bf16.f32 "
        "{%0,%1,%2,%3}, {%4,%5,%6,%7}, {%8,%9}, {%0,%1,%2,%3};\n"
        : "+f"(d[0]), "+f"(d[1]), "+f"(d[2]), "+f"(d[3])
        : "r"(a[0]), "r"(a[1]), "r"(a[2]), "r"(a[3]), "r"(b0), "r"(b1));
}

__device__ __forceinline__ void ldsm4(uint32_t* r, const void* p) {
    uint32_t a = (uint32_t)__cvta_generic_to_shared(p);
    asm volatile("ldmatrix.sync.aligned.m8n8.x4.shared.b16 {%0,%1,%2,%3}, [%4];\n"
                 : "=r"(r[0]), "=r"(r[1]), "=r"(r[2]), "=r"(r[3]) : "r"(a));
}

__device__ __forceinline__ uint32_t pack_bf2(bf16 a, bf16 b) {
    bf162 p{a, b};
    return *(uint32_t*)&p;
}

// ---------------------------------------------------------------------------
// Round-3 proven split-bf16 NT GEMM. BM=128, BN=64, BK=32, 256 threads.
//   acc[m,n] = sum_k A[m,k]*B[n,k]; out = alpha*acc (+bias) (+Cin) (+sigmoid)
// mode: 0 fp32 Cf; 1 hi/lo row-major; 2 hi/lo transposed.
// ---------------------------------------------------------------------------
__global__ void __launch_bounds__(256)
bsgemm(const bf16* __restrict__ Ah, const bf16* __restrict__ Al,
       int lda, long long bsA,
       const bf16* __restrict__ Bh, const bf16* __restrict__ Bl,
       int ldb, long long bsB,
       const float* __restrict__ bias,
       const float* __restrict__ Cin, long long bsCin,
       float* __restrict__ Cf, bf16* __restrict__ Oh, bf16* __restrict__ Ol,
       int ldc, long long bsC,
       int K, float alpha, int mode, int act)
{
    __shared__ __align__(16) bf16 As[2][2][128][24];
    __shared__ __align__(16) bf16 Bs[2][2][64][24];

    const int tid = threadIdx.x;
    const int lane = tid & 31;
    const int warp = tid >> 5;
    const int wm = warp & 3;
    const int wn = warp >> 2;
    const int bx = blockIdx.x, by = blockIdx.y, bz = blockIdx.z;

    const bf16* Abh = Ah + bz * bsA + (long long)by * 128 * lda;
    const bf16* Abl = Al + bz * bsA + (long long)by * 128 * lda;
    const bf16* Bbh = Bh + bz * bsB + (long long)bx * 64 * ldb;
    const bf16* Bbl = Bl + bz * bsB + (long long)bx * 64 * ldb;

    float d[2][4][4];
#pragma unroll
    for (int mt = 0; mt < 2; mt++)
#pragma unroll
        for (int nt = 0; nt < 4; nt++)
#pragma unroll
            for (int e = 0; e < 4; e++) d[mt][nt][e] = 0.f;

    const int arow0 = tid >> 2;
    const int akc   = tid & 3;
    const int brow  = tid >> 2;
    const int ldsr  = lane & 15;
    const int ldsc  = (lane & 16) ? 8 : 0;

    for (int k0 = 0; k0 < K; k0 += 32) {
#pragma unroll
        for (int t = 0; t < 2; t++) {
            int r = arow0 + t * 64;
            const bf16* shp = Abh + (long long)r * lda + k0 + akc * 8;
            const bf16* slp = Abl + (long long)r * lda + k0 + akc * 8;
            *(uint4*)&As[akc >> 1][0][r][(akc & 1) * 8] = *(const uint4*)shp;
            *(uint4*)&As[akc >> 1][1][r][(akc & 1) * 8] = *(const uint4*)slp;
        }
        {
            const bf16* shp = Bbh + (long long)brow * ldb + k0 + akc * 8;
            const bf16* slp = Bbl + (long long)brow * ldb + k0 + akc * 8;
            *(uint4*)&Bs[akc >> 1][0][brow][(akc & 1) * 8] = *(const uint4*)shp;
            *(uint4*)&Bs[akc >> 1][1][brow][(akc & 1) * 8] = *(const uint4*)slp;
        }
        __syncthreads();

#pragma unroll
        for (int kh = 0; kh < 2; kh++) {
            uint32_t ah[2][4], al[2][4], bh[2][4], bl[2][4];
#pragma unroll
            for (int mt = 0; mt < 2; mt++) {
                int r = wm * 32 + mt * 16 + ldsr;
                ldsm4(ah[mt], &As[kh][0][r][ldsc]);
                ldsm4(al[mt], &As[kh][1][r][ldsc]);
            }
#pragma unroll
            for (int np = 0; np < 2; np++) {
                int r = wn * 32 + np * 16 + ldsr;
                ldsm4(bh[np], &Bs[kh][0][r][ldsc]);
                ldsm4(bl[np], &Bs[kh][1][r][ldsc]);
            }
#pragma unroll
            for (int mt = 0; mt < 2; mt++)
#pragma unroll
                for (int nt = 0; nt < 4; nt++) {
                    int np = nt >> 1, sel = nt & 1;
                    uint32_t bh0 = bh[np][sel], bh1 = bh[np][sel + 2];
                    uint32_t bl0 = bl[np][sel], bl1 = bl[np][sel + 2];
                    mma16816(d[mt][nt], ah[mt], bh0, bh1);
                    mma16816(d[mt][nt], ah[mt], bl0, bl1);
                    mma16816(d[mt][nt], al[mt], bh0, bh1);
                }
        }
        __syncthreads();
    }

    const int g = lane >> 2, tig = lane & 3;
    const float* CinB = Cin ? (Cin + bz * bsCin) : nullptr;

#pragma unroll
    for (int mt = 0; mt < 2; mt++) {
#pragma unroll
        for (int nt = 0; nt < 4; nt++) {
            int c = bx * 64 + wn * 32 + nt * 8 + tig * 2;
#pragma unroll
            for (int half = 0; half < 2; half++) {
                int r = by * 128 + wm * 32 + mt * 16 + g + half * 8;
                float v0 = alpha * d[mt][nt][half * 2 + 0];
                float v1 = alpha * d[mt][nt][half * 2 + 1];
                if (CinB) {
                    float2 ci = *(const float2*)(CinB + (long long)r * ldc + c);
                    v0 += ci.x; v1 += ci.y;
                }
                if (bias) { v0 += bias[c]; v1 += bias[c + 1]; }
                if (act == 1) {
                    v0 = 1.f / (1.f + __expf(-v0));
                    v1 = 1.f / (1.f + __expf(-v1));
                }
                if (mode == 0) {
                    float2 ov = {v0, v1};
                    *(float2*)(Cf + bz * bsC + (long long)r * ldc + c) = ov;
                } else if (mode == 1) {
                    bf16 h0, h1, l0, l1;
                    bsplit(v0, h0, l0); bsplit(v1, h1, l1);
                    *(bf162*)(Oh + bz * bsC + (long long)r * ldc + c) = bf162{h0, h1};
                    *(bf162*)(Ol + bz * bsC + (long long)r * ldc + c) = bf162{l0, l1};
                } else {  // transposed [n][m]
                    bf16 h0, h1, l0, l1;
                    bsplit(v0, h0, l0); bsplit(v1, h1, l1);
                    Oh[bz * bsC + (long long)c * ldc + r]       = h0;
                    Oh[bz * bsC + (long long)(c + 1) * ldc + r] = h1;
                    Ol[bz * bsC + (long long)c * ldc + r]       = l0;
                    Ol[bz * bsC + (long long)(c + 1) * ldc + r] = l1;
                }
            }
        }
    }
}

// ---------------------------------------------------------------------------
// Flash-fused attention: logits (0.125*QK^T + z) -> online softmax -> PV.
// CTA = 128 i-rows x 1 head, 256 threads (8 warps x 16 rows). 16 j-tiles of 64.
// K/V^T/z tiles double-buffered via cp.async. P kept hi/lo in registers.
// smem: K[2buf][2hl][4kc][64][24] (49152B) + V same (49152B) + z[2][128][68]f.
// ---------------------------------------------------------------------------
#define FL_VBASE 24576                      // elems: V region after K region
#define FL_ZBYTE 98304                      // byte offset of z region
#define FL_SMEM  (98304 + 2 * 128 * 68 * 4) // 167936 B

__global__ void __launch_bounds__(256, 1)
flash_attn(const bf16* __restrict__ Qh, const bf16* __restrict__ Ql,
           const bf16* __restrict__ Kh, const bf16* __restrict__ Kl,
           const bf16* __restrict__ Vth, const bf16* __restrict__ Vtl,
           const float* __restrict__ Z, float* __restrict__ O)
{
    extern __shared__ __align__(16) char smraw[];
    bf16* sm = (bf16*)smraw;
    float* zs = (float*)(smraw + FL_ZBYTE);
    const int tid = threadIdx.x, lane = tid & 31, w = tid >> 5;
    const int g = lane >> 2, tig = lane & 3;
    const int ldsr = lane & 15, ldsc = (lane & 16) ? 8 : 0;
    const int i0 = blockIdx.x * 128, h = blockIdx.y;
    const uint32_t smb = smem_u32(sm);

    // ---- stage Q (reuses K region), build Q fragments ----
#pragma unroll
    for (int t = 0; t < 8; t++) {
        int lin = tid + t * 256;                 // 0..2047
        int hl = lin >> 10, rem = lin & 1023;
        int r = rem >> 3, ch = rem & 7;
        int kc = ch >> 1, c8 = (ch & 1) * 8;
        const bf16* src = (hl ? Ql : Qh) + (long long)(i0 + r) * NN + h * 64 + kc * 16 + c8;
        cpasync16(smb + (uint32_t)(((hl * 4 + kc) * 128 + r) * 24 + c8) * 2, src);
    }
    cp_commit(); cp_wait<0>();
    __syncthreads();

    uint32_t qfh[4][4], qfl[4][4];
#pragma unroll
    for (int kc = 0; kc < 4; kc++) {
        ldsm4(qfh[kc], sm + ((0 * 4 + kc) * 128 + w * 16 + ldsr) * 24 + ldsc);
        ldsm4(qfl[kc], sm + ((1 * 4 + kc) * 128 + w * 16 + ldsr) * 24 + ldsc);
    }
    __syncthreads();   // staging area about to be overwritten by K tiles

    float o[8][4];
#pragma unroll
    for (int nd = 0; nd < 8; nd++)
#pragma unroll
        for (int e = 0; e < 4; e++) o[nd][e] = 0.f;
    float m0 = -1e30f, m1 = -1e30f, l0 = 0.f, l1 = 0.f;

    auto load_kvz = [&](int buf, int jt) {
        const int j0 = jt * 64;
#pragma unroll
        for (int t = 0; t < 8; t++) {
            int lin = tid + t * 256;             // K then V, 2048 chunks
            int tensor = lin >> 10, rem = lin & 1023;
            int hl = rem >> 9, rem2 = rem & 511;
            int r = rem2 >> 3, ch = rem2 & 7;
            int kc = ch >> 1, c8 = (ch & 1) * 8;
            if (tensor == 0) {
                const bf16* src = (hl ? Kl : Kh) + (long long)(j0 + r) * NN + h * 64 + kc * 16 + c8;
                cpasync16(smb + (uint32_t)((((buf * 2 + hl) * 4 + kc) * 64 + r) * 24 + c8) * 2, src);
            } else {
                const bf16* src = (hl ? Vtl : Vth) + (long long)(h * 64 + r) * NN + j0 + kc * 16 + c8;
                cpasync16(smb + (uint32_t)(FL_VBASE + (((buf * 2 + hl) * 4 + kc) * 64 + r) * 24 + c8) * 2, src);
            }
        }
#pragma unroll
        for (int t = 0; t < 8; t++) {
            int lin = tid + t * 256;             // z: 2048 x 16B
            int r = lin >> 4, ch = lin & 15;
            const float* src = Z + (long long)h * NN * NN + (long long)(i0 + r) * NN + j0 + ch * 4;
            cpasync16(smb + FL_ZBYTE + (uint32_t)(buf * 128 * 68 + r * 68 + ch * 4) * 4, src);
        }
    };

    for (int jt = 0; jt < 16; jt++) {
        const int buf = jt & 1;
        if (jt == 0) { load_kvz(0, 0); cp_commit(); }
        if (jt + 1 < 16) { load_kvz(buf ^ 1, jt + 1); cp_commit(); cp_wait<1>(); }
        else             { cp_wait<0>(); }
        __syncthreads();

        // ---- S = Q @ K^T (3-term hi/lo) ----
        float s[8][4];
#pragma unroll
        for (int nf = 0; nf < 8; nf++)
#pragma unroll
            for (int e = 0; e < 4; e++) s[nf][e] = 0.f;

#pragma unroll
        for (int kc = 0; kc < 4; kc++) {
            uint32_t bh[4][4], bl[4][4];
#pragma unroll
            for (int np = 0; np < 4; np++) {
                ldsm4(bh[np], sm + (((buf * 2 + 0) * 4 + kc) * 64 + np * 16 + ldsr) * 24 + ldsc);
                ldsm4(bl[np], sm + (((buf * 2 + 1) * 4 + kc) * 64 + np * 16 + ldsr) * 24 + ldsc);
            }
#pragma unroll
            for (int nf = 0; nf < 8; nf++) {
                int np = nf >> 1, sel = nf & 1;
                mma16816(s[nf], qfh[kc], bh[np][sel], bh[np][sel + 2]);
                mma16816(s[nf], qfh[kc], bl[np][sel], bl[np][sel + 2]);
                mma16816(s[nf], qfl[kc], bh[np][sel], bh[np][sel + 2]);
            }
        }

        // ---- add z, scale; row max over tile ----
        const float* zr0 = zs + buf * 128 * 68 + (w * 16 + g) * 68;
        const float* zr1 = zr0 + 8 * 68;
        float mx0 = -1e30f, mx1 = -1e30f;
#pragma unroll
        for (int nf = 0; nf < 8; nf++) {
            float2 z0 = *(const float2*)(zr0 + nf * 8 + 2 * tig);
            float2 z1 = *(const float2*)(zr1 + nf * 8 + 2 * tig);
            s[nf][0] = fmaf(s[nf][0], 0.125f, z0.x);
            s[nf][1] = fmaf(s[nf][1], 0.125f, z0.y);
            s[nf][2] = fmaf(s[nf][2], 0.125f, z1.x);
            s[nf][3] = fmaf(s[nf][3], 0.125f, z1.y);
            mx0 = fmaxf(mx0, fmaxf(s[nf][0], s[nf][1]));
            mx1 = fmaxf(mx1, fmaxf(s[nf][2], s[nf][3]));
        }
        mx0 = fmaxf(mx0, __shfl_xor_sync(0xffffffffu, mx0, 1));
        mx0 = fmaxf(mx0, __shfl_xor_sync(0xffffffffu, mx0, 2));
        mx1 = fmaxf(mx1, __shfl_xor_sync(0xffffffffu, mx1, 1));
        mx1 = fmaxf(mx1, __shfl_xor_sync(0xffffffffu, mx1, 2));

        const float mn0 = fmaxf(m0, mx0), mn1 = fmaxf(m1, mx1);
        const float sc0 = __expf(m0 - mn0), sc1 = __expf(m1 - mn1);

        // ---- P = exp(S - m); pack A-fragments hi/lo; row sums ----
        float rs0 = 0.f, rs1 = 0.f;
        uint32_t phi[4][4], plo[4][4];
#pragma unroll
        for (int nf = 0; nf < 8; nf++) {
            float p0 = __expf(s[nf][0] - mn0);
            float p1 = __expf(s[nf][1] - mn0);
            float p2 = __expf(s[nf][2] - mn1);
            float p3 = __expf(s[nf][3] - mn1);
            rs0 += p0 + p1; rs1 += p2 + p3;
            bf16 h0, e0, h1, e1, h2, e2, h3, e3;
            bsplit(p0, h0, e0); bsplit(p1, h1, e1);
            bsplit(p2, h2, e2); bsplit(p3, h3, e3);
            int kc = nf >> 1, which = (nf & 1) * 2;
            phi[kc][which + 0] = pack_bf2(h0, h1);
            phi[kc][which + 1] = pack_bf2(h2, h3);
            plo[kc][which + 0] = pack_bf2(e0, e1);
            plo[kc][which + 1] = pack_bf2(e2, e3);
        }
        rs0 += __shfl_xor_sync(0xffffffffu, rs0, 1);
        rs0 += __shfl_xor_sync(0xffffffffu, rs0, 2);
        rs1 += __shfl_xor_sync(0xffffffffu, rs1, 1);
        rs1 += __shfl_xor_sync(0xffffffffu, rs1, 2);
        l0 = l0 * sc0 + rs0;  l1 = l1 * sc1 + rs1;
        m0 = mn0;  m1 = mn1;
#pragma unroll
        for (int nd = 0; nd < 8; nd++) {
            o[nd][0] *= sc0; o[nd][1] *= sc0;
            o[nd][2] *= sc1; o[nd][3] *= sc1;
        }

        // ---- O += P @ V (3-term) ----
#pragma unroll
        for (int kc = 0; kc < 4; kc++) {
            uint32_t vh[4][4], vl[4][4];
#pragma unroll
            for (int np = 0; np < 4; np++) {
                ldsm4(vh[np], sm + FL_VBASE + (((buf * 2 + 0) * 4 + kc) * 64 + np * 16 + ldsr) * 24 + ldsc);
                ldsm4(vl[np], sm + FL_VBASE + (((buf * 2 + 1) * 4 + kc) * 64 + np * 16 + ldsr) * 24 + ldsc);
            }
#pragma unroll
            for (int nd = 0; nd < 8; nd++) {
                int np = nd >> 1, sel = nd & 1;
                mma16816(o[nd], phi[kc], vh[np][sel], vh[np][sel + 2]);
                mma16816(o[nd], phi[kc], vl[np][sel], vl[np][sel + 2]);
                mma16816(o[nd], plo[kc], vh[np][sel], vh[np][sel + 2]);
            }
        }
        __syncthreads();
    }

    // ---- finalize: divide by l, store ----
    const float inv0 = 1.f / l0, inv1 = 1.f / l1;
    float* or0 = O + (long long)(i0 + w * 16 + g) * NN + h * 64;
    float* or1 = or0 + 8 * NN;
#pragma unroll
    for (int nd = 0; nd < 8; nd++) {
        float2 a{o[nd][0] * inv0, o[nd][1] * inv0};
        float2 b{o[nd][2] * inv1, o[nd][3] * inv1};
        *(float2*)(or0 + nd * 8 + 2 * tig) = a;
        *(float2*)(or1 + nd * 8 + 2 * tig) = b;
    }
}

// ---------------------------------------------------------------------------
// fused fp32 -> bf16 hi/lo split for 7 tensors (grid.y = tensor)
// ---------------------------------------------------------------------------
struct SplitJobs {
    const float* src[7];
    bf16* dh[7];
    bf16* dl[7];
};

__global__ void __launch_bounds__(256)
conv_split7(SplitJobs js)
{
    const float* x = js.src[blockIdx.y];
    bf16* xh = js.dh[blockIdx.y];
    bf16* xl = js.dl[blockIdx.y];
    int idx = blockIdx.x * 256 + threadIdx.x;
    float4 v = ((const float4*)x)[idx];
    bf16 h0, h1, h2, h3, l0, l1, l2, l3;
    bsplit(v.x, h0, l0); bsplit(v.y, h1, l1);
    bsplit(v.z, h2, l2); bsplit(v.w, h3, l3);
    bf162* H = (bf162*)(xh + idx * 4);
    bf162* L = (bf162*)(xl + idx * 4);
    H[0] = bf162{h0, h1}; H[1] = bf162{h2, h3};
    L[0] = bf162{l0, l1}; L[1] = bf162{l2, l3};
}

// ---------------------------------------------------------------------------
// z projection: z[h, p] = sum_c bias[p, c] * Wz[c, h] + (1-mask[j])*(-1e6)
// ---------------------------------------------------------------------------
__global__ void __launch_bounds__(128)
zproj_kernel(const float* __restrict__ bias, const float* __restrict__ Wz,
             const float* __restrict__ mask, float* __restrict__ z)
{
    __shared__ float bs[64][129];
    __shared__ float wzs[128][16];

    const int tid = threadIdx.x;
    const long long p0 = (long long)blockIdx.x * 64;

    for (int e = tid; e < CZ * HEADS; e += 128)
        wzs[e >> 4][e & 15] = Wz[e];

    const int c4 = tid & 31;
    const int r0 = tid >> 5;
#pragma unroll
    for (int r = r0; r < 64; r += 4) {
        float4 v = *(const float4*)(bias + (p0 + r) * CZ + c4 * 4);
        bs[r][c4 * 4 + 0] = v.x;
        bs[r][c4 * 4 + 1] = v.y;
        bs[r][c4 * 4 + 2] = v.z;
        bs[r][c4 * 4 + 3] = v.w;
    }
    __syncthreads();

    const int pair = tid & 63;
    const int hh = (tid >> 6) * 8;

    float acc[8];
#pragma unroll
    for (int h = 0; h < 8; h++) acc[h] = 0.f;

#pragma unroll 8
    for (int c = 0; c < CZ; c++) {
        float bv = bs[pair][c];
        float4 w0 = *(const float4*)&wzs[c][hh];
        float4 w1 = *(const float4*)&wzs[c][hh + 4];
        acc[0] += bv * w0.x; acc[1] += bv * w0.y;
        acc[2] += bv * w0.z; acc[3] += bv * w0.w;
        acc[4] += bv * w1.x; acc[5] += bv * w1.y;
        acc[6] += bv * w1.z; acc[7] += bv * w1.w;
    }

    const long long p = p0 + pair;
    const int j = (int)(p & (NN - 1));
    const float madd = (1.0f - mask[j]) * (-1000000.0f);
#pragma unroll
    for (int h = 0; h < 8; h++)
        z[(long long)(hh + h) * (NN * NN) + p] = acc[h] + madd;
}

// ---------------------------------------------------------------------------
// go = g * o -> bf16 hi/lo
// ---------------------------------------------------------------------------
__global__ void __launch_bounds__(256)
mul_split_kernel(const float* __restrict__ a, const float* __restrict__ b,
                 bf16* __restrict__ ch, bf16* __restrict__ cl)
{
    int idx = blockIdx.x * 256 + threadIdx.x;
    float4 av = ((const float4*)a)[idx];
    float4 bv = ((const float4*)b)[idx];
    float4 cv;
    cv.x = av.x * bv.x; cv.y = av.y * bv.y;
    cv.z = av.z * bv.z; cv.w = av.w * bv.w;
    bf16 h0, h1, h2, h3, l0, l1, l2, l3;
    bsplit(cv.x, h0, l0); bsplit(cv.y, h1, l1);
    bsplit(cv.z, h2, l2); bsplit(cv.w, h3, l3);
    bf162* H = (bf162*)(ch + idx * 4);
    bf162* L = (bf162*)(cl + idx * 4);
    H[0] = bf162{h0, h1}; H[1] = bf162{h2, h3};
    L[0] = bf162{l0, l1}; L[1] = bf162{l2, l3};
}

// ---------------------------------------------------------------------------
extern "C" void kernel_launch(void* const* d_in, const int* in_sizes, int n_in,
                              void* d_out, int out_size)
{
    (void)in_sizes; (void)n_in; (void)out_size;

    const float* s    = (const float*)d_in[0];
    const float* kin  = (const float*)d_in[1];
    const float* mask = (const float*)d_in[2];
    const float* bias = (const float*)d_in[3];
    const float* Wq   = (const float*)d_in[4];
    const float* bq   = (const float*)d_in[5];
    const float* Wk   = (const float*)d_in[6];
    const float* Wv   = (const float*)d_in[7];
    const float* Wg   = (const float*)d_in[8];
    const float* Wo   = (const float*)d_in[9];
    const float* Wz   = (const float*)d_in[10];
    float* out = (float*)d_out;

    bf16 *sh, *sl, *kih, *kil, *Wqh, *Wql, *Wkh, *Wkl, *Wvh, *Wvl;
    bf16 *Wgh, *Wgl, *Woh, *Wol, *qh, *ql, *kh, *kl, *vth, *vtl;
    bf16 *goh, *gol;
    float *gg, *z, *o;
    cudaGetSymbolAddress((void**)&sh,  g_sh);  cudaGetSymbolAddress((void**)&sl,  g_sl);
    cudaGetSymbolAddress((void**)&kih, g_kih); cudaGetSymbolAddress((void**)&kil, g_kil);
    cudaGetSymbolAddress((void**)&Wqh, g_Wqh); cudaGetSymbolAddress((void**)&Wql, g_Wql);
    cudaGetSymbolAddress((void**)&Wkh, g_Wkh); cudaGetSymbolAddress((void**)&Wkl, g_Wkl);
    cudaGetSymbolAddress((void**)&Wvh, g_Wvh); cudaGetSymbolAddress((void**)&Wvl, g_Wvl);
    cudaGetSymbolAddress((void**)&Wgh, g_Wgh); cudaGetSymbolAddress((void**)&Wgl, g_Wgl);
    cudaGetSymbolAddress((void**)&Woh, g_Woh); cudaGetSymbolAddress((void**)&Wol, g_Wol);
    cudaGetSymbolAddress((void**)&qh,  g_qh);  cudaGetSymbolAddress((void**)&ql,  g_ql);
    cudaGetSymbolAddress((void**)&kh,  g_kh);  cudaGetSymbolAddress((void**)&kl,  g_kl);
    cudaGetSymbolAddress((void**)&vth, g_vth); cudaGetSymbolAddress((void**)&vtl, g_vtl);
    cudaGetSymbolAddress((void**)&goh, g_goh); cudaGetSymbolAddress((void**)&gol, g_gol);
    cudaGetSymbolAddress((void**)&gg,  g_g);
    cudaGetSymbolAddress((void**)&z,   g_z);
    cudaGetSymbolAddress((void**)&o,   g_o);

    cudaFuncSetAttribute(flash_attn, cudaFuncAttributeMaxDynamicSharedMemorySize,
                         FL_SMEM);

    // split fp32 operands to hi/lo
    SplitJobs sj;
    sj.src[0] = s;   sj.dh[0] = sh;  sj.dl[0] = sl;
    sj.src[1] = kin; sj.dh[1] = kih; sj.dl[1] = kil;
    sj.src[2] = Wq;  sj.dh[2] = Wqh; sj.dl[2] = Wql;
    sj.src[3] = Wk;  sj.dh[3] = Wkh; sj.dl[3] = Wkl;
    sj.src[4] = Wv;  sj.dh[4] = Wvh; sj.dl[4] = Wvl;
    sj.src[5] = Wg;  sj.dh[5] = Wgh; sj.dl[5] = Wgl;
    sj.src[6] = Wo;  sj.dh[6] = Woh; sj.dl[6] = Wol;
    conv_split7<<<dim3((NN * NN) / (256 * 4), 7), 256>>>(sj);

    dim3 gsq(16, 8, 1);
    // q = s @ Wq^T + bq  -> hi/lo
    bsgemm<<<gsq, 256>>>(sh, sl, NN, 0, Wqh, Wql, NN, 0, bq,
                         nullptr, 0, nullptr, qh, ql, NN, 0, NN, 1.f, 1, 0);
    // k = kin @ Wk^T -> hi/lo
    bsgemm<<<gsq, 256>>>(kih, kil, NN, 0, Wkh, Wkl, NN, 0, nullptr,
                         nullptr, 0, nullptr, kh, kl, NN, 0, NN, 1.f, 1, 0);
    // vT = (kin @ Wv^T)^T -> hi/lo transposed [c_s][j]
    bsgemm<<<gsq, 256>>>(kih, kil, NN, 0, Wvh, Wvl, NN, 0, nullptr,
                         nullptr, 0, nullptr, vth, vtl, NN, 0, NN, 1.f, 2, 0);
    // g = sigmoid(s @ Wg^T) -> fp32
    bsgemm<<<gsq, 256>>>(sh, sl, NN, 0, Wgh, Wgl, NN, 0, nullptr,
                         nullptr, 0, gg, nullptr, nullptr, NN, 0, NN, 1.f, 0, 1);
    // z = bias @ Wz + mask
    zproj_kernel<<<(NN * NN) / 64, 128>>>(bias, Wz, mask, z);
    // fused logits + softmax + PV
    flash_attn<<<dim3(8, HEADS), 256, FL_SMEM>>>(qh, ql, kh, kl, vth, vtl, z, o);
    // go = g * o -> hi/lo
    mul_split_kernel<<<(NN * NN) / (256 * 4), 256>>>(gg, o, goh, gol);
    // out = go @ Wo^T -> fp32
    bsgemm<<<gsq, 256>>>(goh, gol, NN, 0, Woh, Wol, NN, 0, nullptr,
                         nullptr, 0, out, nullptr, nullptr, NN, 0, NN, 1.f, 0, 0);
}